// round 13
// baseline (speedup 1.0000x reference)
#include <cuda_runtime.h>
#include <cstdint>
#include <cstddef>

#define NB 256
#define FIN 784
#define FH 500
#define NT 100
#define J 25600                 /* NB*NT flattened column dim */
#define NELEM (FH*J)            /* 12,800,000 */

#define EMC 0.7788007830714049f
#define A1C 1.1466802242428472f
#define A2C (-0.2865047968601901f)

// ---------------- scratch (device globals) -----------------------------------
__device__ float g_xT[FIN * J];      // X transposed to [f][J]
__device__ float g_w1Td[FIN * 2048]; // W1 transposed+duplicated [k][2c,2c+1]:
                                     // c 0..499 mu row c, 500..999 lv, rest 0
__device__ float g_w2Td[512 * 1024]; // W2 transposed+duplicated, zero-padded
__device__ float g_psp2[NELEM];      // coding -> (IIR in place) psp2, [f][J]
__device__ float g_cur2[NELEM];      // [f][J]
__device__ float g_psp3[NELEM];      // [f][J]
__device__ float g_cur3[10 * J];     // [o][J]

// ---------------- cp.async helpers -------------------------------------------
__device__ __forceinline__ uint32_t smem_u32(const void* p) {
  return (uint32_t)__cvta_generic_to_shared(p);
}
__device__ __forceinline__ void cp_async16(uint32_t s, const void* g) {
  asm volatile("cp.async.cg.shared.global [%0], [%1], 16;" :: "r"(s), "l"(g));
}
__device__ __forceinline__ void cp_async16z(uint32_t s, const void* g, bool p) {
  int sz = p ? 16 : 0;
  asm volatile("cp.async.cg.shared.global [%0], [%1], 16, %2;"
               :: "r"(s), "l"(g), "r"(sz));
}
#define CP_COMMIT() asm volatile("cp.async.commit_group;")
#define CP_WAIT0()  asm volatile("cp.async.wait_group 0;" ::: "memory")

// ---------------- packed fp32x2 FMA (Blackwell FFMA2) ------------------------
__device__ __forceinline__ void fma2(unsigned long long& d,
                                     unsigned long long a,
                                     unsigned long long b) {
  asm("fma.rn.f32x2 %0, %1, %2, %3;" : "=l"(d) : "l"(a), "l"(b), "l"(d));
}
__device__ __forceinline__ float2 unpack2(unsigned long long v) {
  float lo, hi;
  asm("mov.b64 {%0, %1}, %2;" : "=f"(lo), "=f"(hi) : "l"(v));
  return make_float2(lo, hi);
}

// ---------------- JAX threefry-2x32, key = (0, 42) ---------------------------
__device__ __forceinline__ uint32_t rotl32(uint32_t v, int d) {
  return (v << d) | (v >> (32 - d));
}

__device__ __forceinline__ void threefry_0_42(uint32_t x0, uint32_t x1,
                                              uint32_t& o0, uint32_t& o1) {
  const uint32_t ks1 = 42u;
  const uint32_t ks2 = 0x1BD11BDAu ^ 42u;
  x1 += ks1;
#define TF_R(d) { x0 += x1; x1 = rotl32(x1, d); x1 ^= x0; }
  TF_R(13) TF_R(15) TF_R(26) TF_R(6)
  x0 += ks1; x1 += ks2 + 1u;
  TF_R(17) TF_R(29) TF_R(16) TF_R(24)
  x0 += ks2; x1 += 2u;
  TF_R(13) TF_R(15) TF_R(26) TF_R(6)
  x0 += 0u; x1 += ks1 + 3u;
  TF_R(17) TF_R(29) TF_R(16) TF_R(24)
  x0 += ks1; x1 += ks2 + 4u;
  TF_R(13) TF_R(15) TF_R(26) TF_R(6)
  x0 += ks2; x1 += 5u;
#undef TF_R
  o0 = x0; o1 = x1;
}

__device__ __forceinline__ float erfinv_xla(float x) {
  float nx2 = __fmul_rn(x, x);
  float w = -log1pf(-nx2);
  float p;
  if (w < 5.0f) {
    w = __fadd_rn(w, -2.5f);
    p = 2.81022636e-08f;
    p = __fadd_rn(3.43273939e-07f, __fmul_rn(p, w));
    p = __fadd_rn(-3.5233877e-06f, __fmul_rn(p, w));
    p = __fadd_rn(-4.39150654e-06f, __fmul_rn(p, w));
    p = __fadd_rn(0.00021858087f, __fmul_rn(p, w));
    p = __fadd_rn(-0.00125372503f, __fmul_rn(p, w));
    p = __fadd_rn(-0.00417768164f, __fmul_rn(p, w));
    p = __fadd_rn(0.246640727f, __fmul_rn(p, w));
    p = __fadd_rn(1.50140941f, __fmul_rn(p, w));
  } else {
    w = __fadd_rn(sqrtf(w), -3.0f);
    p = -0.000200214257f;
    p = __fadd_rn(0.000100950558f, __fmul_rn(p, w));
    p = __fadd_rn(0.00134934322f, __fmul_rn(p, w));
    p = __fadd_rn(-0.00367342844f, __fmul_rn(p, w));
    p = __fadd_rn(0.00573950773f, __fmul_rn(p, w));
    p = __fadd_rn(-0.0076224613f, __fmul_rn(p, w));
    p = __fadd_rn(0.00943887047f, __fmul_rn(p, w));
    p = __fadd_rn(1.00167406f, __fmul_rn(p, w));
    p = __fadd_rn(2.83297682f, __fmul_rn(p, w));
  }
  return __fmul_rn(p, x);
}

__device__ __forceinline__ float eps_at(uint32_t ctr) {
  uint32_t r0, r1;
  threefry_0_42(0u, ctr, r0, r1);
  uint32_t bits = r0 ^ r1;
  const float lo = -0.99999994039535522461f;
  float f = __fadd_rn(__uint_as_float((bits >> 9) | 0x3f800000u), -1.0f);
  float u = __fadd_rn(__fmul_rn(f, 2.0f), lo);
  u = fmaxf(u, lo);
  return __fmul_rn(1.4142135623730951f, erfinv_xla(u));
}

// ---------------- kernel 0a: transpose X -> g_xT[f][J] -----------------------
__global__ __launch_bounds__(256) void xT_kernel(const float* __restrict__ X) {
  int f = blockIdx.y;
  int j = blockIdx.x * 256 + threadIdx.x;
  int b = j / NT, t = j - b * NT;
  g_xT[(size_t)f * J + j] = X[(size_t)b * (FIN * NT) + f * NT + t];
}

// ---------------- kernel 0b: transpose+dup W1 -> g_w1Td[k][2048] -------------
__global__ __launch_bounds__(256) void w1T_kernel(const float* __restrict__ W1) {
  int k = blockIdx.x;
  for (int c = threadIdx.x; c < 1024; c += 256) {
    float v = (c < 1000) ? W1[(size_t)c * FIN + k] : 0.f;
    g_w1Td[(size_t)k * 2048 + 2 * c]     = v;
    g_w1Td[(size_t)k * 2048 + 2 * c + 1] = v;
  }
}

// ---------------- kernel 0c: transpose+dup W2 -> g_w2Td[512][1024] -----------
__global__ __launch_bounds__(256) void w2T_kernel(const float* __restrict__ W2) {
  int k = blockIdx.x;
  for (int c = threadIdx.x; c < 512; c += 256) {
    float v = (c < FH && k < FH) ? W2[(size_t)c * FH + k] : 0.f;
    g_w2Td[(size_t)k * 1024 + 2 * c]     = v;
    g_w2Td[(size_t)k * 1024 + 2 * c + 1] = v;
  }
}

// ---------------- kernel 1: GEMM1 + relu + coding(+eps) -> g_psp2[f][J] ------
// Block tile: 64 M-rows (32 mu + 32 lv) x 128 j. 128 threads, 8x8 thread tile.
// A operand pre-duplicated in gmem/smem -> no pack MOVs in the inner loop.
__global__ __launch_bounds__(128, 4) void gemm1_kernel(
    const float* __restrict__ b1) {
  __shared__ float Xs[2][16][128];
  __shared__ float Ws[2][16][136];     // 64 mu-dup | 64 lv-dup | pad
  int f0 = blockIdx.x * 32;
  int j0 = blockIdx.y * 128;
  int tid = threadIdx.x;
  int tx = tid & 15, ty = tid >> 4;      // ty 0..7 -> 4 f rows each

  int kk_s = tid >> 3;                   // 0..15
  int q8   = tid & 7;                    // 0..7
  const float* xsrc = g_xT + j0 + q8 * 4;
  const float* wmu  = g_w1Td + 2 * f0 + q8 * 4;          // mu dup cols
  const float* wlv  = g_w1Td + 2 * (500 + f0) + q8 * 4;  // lv dup cols

  unsigned long long acc2[8][4];
#pragma unroll
  for (int i = 0; i < 8; i++)
#pragma unroll
    for (int p = 0; p < 4; p++) acc2[i][p] = 0ull;

  const int NCH = FIN / 16;              // 49 exact chunks

  // prologue: chunk 0 into buffer 0
#pragma unroll
  for (int s = 0; s < 4; s++)
    cp_async16(smem_u32(&Xs[0][kk_s][q8 * 4 + s * 32]),
               xsrc + (size_t)kk_s * J + s * 32);
#pragma unroll
  for (int s = 0; s < 2; s++) {
    cp_async16(smem_u32(&Ws[0][kk_s][q8 * 4 + s * 32]),
               wmu + (size_t)kk_s * 2048 + s * 32);
    cp_async16(smem_u32(&Ws[0][kk_s][64 + q8 * 4 + s * 32]),
               wlv + (size_t)kk_s * 2048 + s * 32);
  }
  CP_COMMIT();
  CP_WAIT0();
  __syncthreads();

#pragma unroll 1
  for (int c = 0; c < NCH; c++) {
    int cur = c & 1;
    bool more = (c + 1 < NCH);
    if (more) {
      int k0 = (c + 1) * 16;
#pragma unroll
      for (int s = 0; s < 4; s++)
        cp_async16(smem_u32(&Xs[cur ^ 1][kk_s][q8 * 4 + s * 32]),
                   xsrc + (size_t)(k0 + kk_s) * J + s * 32);
#pragma unroll
      for (int s = 0; s < 2; s++) {
        cp_async16(smem_u32(&Ws[cur ^ 1][kk_s][q8 * 4 + s * 32]),
                   wmu + (size_t)(k0 + kk_s) * 2048 + s * 32);
        cp_async16(smem_u32(&Ws[cur ^ 1][kk_s][64 + q8 * 4 + s * 32]),
                   wlv + (size_t)(k0 + kk_s) * 2048 + s * 32);
      }
      CP_COMMIT();
    }
#pragma unroll
    for (int kk = 0; kk < 16; kk++) {
      ulonglong2 bq0 = *reinterpret_cast<const ulonglong2*>(&Xs[cur][kk][tx * 4]);
      ulonglong2 bq1 = *reinterpret_cast<const ulonglong2*>(&Xs[cur][kk][tx * 4 + 64]);
      unsigned long long bp[4] = {bq0.x, bq0.y, bq1.x, bq1.y};
      {
        ulonglong2 a0 = *reinterpret_cast<const ulonglong2*>(&Ws[cur][kk][ty * 8]);
        ulonglong2 a1 = *reinterpret_cast<const ulonglong2*>(&Ws[cur][kk][ty * 8 + 4]);
        unsigned long long ap[4] = {a0.x, a0.y, a1.x, a1.y};
#pragma unroll
        for (int i = 0; i < 4; i++)
#pragma unroll
          for (int p = 0; p < 4; p++) fma2(acc2[i][p], ap[i], bp[p]);
      }
      {
        ulonglong2 a0 = *reinterpret_cast<const ulonglong2*>(&Ws[cur][kk][64 + ty * 8]);
        ulonglong2 a1 = *reinterpret_cast<const ulonglong2*>(&Ws[cur][kk][64 + ty * 8 + 4]);
        unsigned long long ap[4] = {a0.x, a0.y, a1.x, a1.y};
#pragma unroll
        for (int i = 0; i < 4; i++)
#pragma unroll
          for (int p = 0; p < 4; p++) fma2(acc2[i + 4][p], ap[i], bp[p]);
      }
    }
    if (more) {
      CP_WAIT0();
      __syncthreads();
    }
  }

  // epilogue: acc2[i] (i<4) = mu row f0+ty*4+i; acc2[i+4] = paired lnvar row.
#pragma unroll
  for (int i = 0; i < 4; i++) {
    int f = f0 + ty * 4 + i;
    if (f >= FH) continue;
    float bm = b1[f], bl = b1[f + FH];
#pragma unroll
    for (int h = 0; h < 2; h++) {
      int jb = j0 + h * 64 + tx * 4;
      float2 m0 = unpack2(acc2[i][h * 2]);
      float2 m1 = unpack2(acc2[i][h * 2 + 1]);
      float2 l0 = unpack2(acc2[i + 4][h * 2]);
      float2 l1 = unpack2(acc2[i + 4][h * 2 + 1]);
      float am[4] = {m0.x, m0.y, m1.x, m1.y};
      float al[4] = {l0.x, l0.y, l1.x, l1.y};
      float o[4];
#pragma unroll
      for (int r = 0; r < 4; r++) {
        int j = jb + r;
        int b = j / NT, t = j - b * NT;
        float mu = fmaxf(__fadd_rn(am[r], bm), 0.f);
        float lv = fmaxf(__fadd_rn(al[r], bl), 0.f);
        float sg = expf(__fmul_rn(0.5f, lv));
        float ev = eps_at((uint32_t)b * 50000u + (uint32_t)f * 100u + (uint32_t)t);
        o[r] = __fadd_rn(mu, __fmul_rn(ev, sg));
      }
      *reinterpret_cast<float4*>(g_psp2 + (size_t)f * J + jb) =
          make_float4(o[0], o[1], o[2], o[3]);
    }
  }
}

// ---------------- kernel 2: dual-exp IIR in place on g_psp2 ------------------
__global__ __launch_bounds__(256) void iir_kernel() {
  __shared__ float s[64 * 101];
  size_t row0 = (size_t)blockIdx.x * 64;
  int tid = threadIdx.x;
  for (int i = tid; i < 6400; i += 256) {
    int r = i / 100, t = i - r * 100;
    s[r * 101 + t] = g_psp2[row0 * 100 + i];
  }
  __syncthreads();
  if (tid < 64) {
    float y1 = 0.f, y2 = 0.f;
    float* row = s + tid * 101;
#pragma unroll
    for (int t = 0; t < NT; t++) {
      float y = __fadd_rn(__fadd_rn(__fmul_rn(A1C, y1), __fmul_rn(A2C, y2)),
                          row[t]);
      row[t] = y;
      y2 = y1; y1 = y;
    }
  }
  __syncthreads();
  for (int i = tid; i < 6400; i += 256) {
    int r = i / 100, t = i - r * 100;
    g_psp2[row0 * 100 + i] = s[r * 101 + t];
  }
}

// ---------------- kernel 3: GEMM2 -> g_cur2[f][J] ----------------------------
// Block tile 64f x 128j, 128 threads, 8x8; dup-A layout, no pack MOVs.
__global__ __launch_bounds__(128, 4) void gemm2_kernel(
    const float* __restrict__ b2) {
  __shared__ float Xs[2][16][128];
  __shared__ float Ws[2][16][136];
  int f0 = blockIdx.x * 64;
  int j0 = blockIdx.y * 128;
  int tid = threadIdx.x;
  int tx = tid & 15, ty = tid >> 4;

  int kk_s = tid >> 3;                   // 0..15
  int q8   = tid & 7;                    // 0..7
  const float* xsrc = g_psp2 + j0 + q8 * 4;
  const float* wsrc = g_w2Td + 2 * f0 + q8 * 4;

  unsigned long long acc2[8][4];
#pragma unroll
  for (int i = 0; i < 8; i++)
#pragma unroll
    for (int p = 0; p < 4; p++) acc2[i][p] = 0ull;

  const int NCH = 32;                    // 512 k padded

  // prologue: chunk 0
  {
    bool xp = (kk_s < FH);
#pragma unroll
    for (int s = 0; s < 4; s++)
      cp_async16z(smem_u32(&Xs[0][kk_s][q8 * 4 + s * 32]),
                  xsrc + (size_t)kk_s * J + s * 32, xp);
#pragma unroll
    for (int s = 0; s < 4; s++)
      cp_async16(smem_u32(&Ws[0][kk_s][q8 * 4 + s * 32]),
                 wsrc + (size_t)kk_s * 1024 + s * 32);
    CP_COMMIT();
    CP_WAIT0();
    __syncthreads();
  }

#pragma unroll 1
  for (int c = 0; c < NCH; c++) {
    int cur = c & 1;
    bool more = (c + 1 < NCH);
    if (more) {
      int k0 = (c + 1) * 16;
      bool xp = (k0 + kk_s < FH);
#pragma unroll
      for (int s = 0; s < 4; s++)
        cp_async16z(smem_u32(&Xs[cur ^ 1][kk_s][q8 * 4 + s * 32]),
                    xsrc + (size_t)(k0 + kk_s) * J + s * 32, xp);
#pragma unroll
      for (int s = 0; s < 4; s++)
        cp_async16(smem_u32(&Ws[cur ^ 1][kk_s][q8 * 4 + s * 32]),
                   wsrc + (size_t)(k0 + kk_s) * 1024 + s * 32);
      CP_COMMIT();
    }
#pragma unroll
    for (int kk = 0; kk < 16; kk++) {
      ulonglong2 bq0 = *reinterpret_cast<const ulonglong2*>(&Xs[cur][kk][tx * 4]);
      ulonglong2 bq1 = *reinterpret_cast<const ulonglong2*>(&Xs[cur][kk][tx * 4 + 64]);
      unsigned long long bp[4] = {bq0.x, bq0.y, bq1.x, bq1.y};
      {
        ulonglong2 a0 = *reinterpret_cast<const ulonglong2*>(&Ws[cur][kk][ty * 8]);
        ulonglong2 a1 = *reinterpret_cast<const ulonglong2*>(&Ws[cur][kk][ty * 8 + 4]);
        unsigned long long ap[4] = {a0.x, a0.y, a1.x, a1.y};
#pragma unroll
        for (int i = 0; i < 4; i++)
#pragma unroll
          for (int p = 0; p < 4; p++) fma2(acc2[i][p], ap[i], bp[p]);
      }
      {
        ulonglong2 a0 = *reinterpret_cast<const ulonglong2*>(&Ws[cur][kk][64 + ty * 8]);
        ulonglong2 a1 = *reinterpret_cast<const ulonglong2*>(&Ws[cur][kk][64 + ty * 8 + 4]);
        unsigned long long ap[4] = {a0.x, a0.y, a1.x, a1.y};
#pragma unroll
        for (int i = 0; i < 4; i++)
#pragma unroll
          for (int p = 0; p < 4; p++) fma2(acc2[i + 4][p], ap[i], bp[p]);
      }
    }
    if (more) {
      CP_WAIT0();
      __syncthreads();
    }
  }

#pragma unroll
  for (int i = 0; i < 8; i++) {
    int f = f0 + ((i < 4) ? (ty * 4 + i) : (32 + ty * 4 + i - 4));
    if (f >= FH) continue;
    float bb = b2[f];
#pragma unroll
    for (int h = 0; h < 2; h++) {
      int jb = j0 + h * 64 + tx * 4;
      float2 c0 = unpack2(acc2[i][h * 2]);
      float2 c1 = unpack2(acc2[i][h * 2 + 1]);
      float ac[4] = {c0.x, c0.y, c1.x, c1.y};
      float o[4];
#pragma unroll
      for (int r = 0; r < 4; r++)
        o[r] = __fadd_rn(ac[r], bb);
      *reinterpret_cast<float4*>(g_cur2 + (size_t)f * J + jb) =
          make_float4(o[0], o[1], o[2], o[3]);
    }
  }
}

// ---------------- kernel 4: LIF + second IIR: g_cur2 -> g_psp3 ---------------
__global__ __launch_bounds__(256) void lifiir_kernel() {
  __shared__ float s[64 * 101];
  size_t row0 = (size_t)blockIdx.x * 64;
  int tid = threadIdx.x;
  for (int i = tid; i < 6400; i += 256) {
    int r = i / 100, t = i - r * 100;
    s[r * 101 + t] = g_cur2[row0 * 100 + i];
  }
  __syncthreads();
  if (tid < 64) {
    float v = 0.f, sp = 0.f, y1 = 0.f, y2 = 0.f;
    float* row = s + tid * 101;
#pragma unroll
    for (int t = 0; t < NT; t++) {
      v = __fadd_rn(__fmul_rn(__fmul_rn(v, EMC), __fadd_rn(1.0f, -sp)), row[t]);
      sp = (v > 1.0f) ? 1.0f : 0.f;
      float y = __fadd_rn(__fadd_rn(__fmul_rn(A1C, y1), __fmul_rn(A2C, y2)), sp);
      row[t] = y;
      y2 = y1; y1 = y;
    }
  }
  __syncthreads();
  for (int i = tid; i < 6400; i += 256) {
    int r = i / 100, t = i - r * 100;
    g_psp3[row0 * 100 + i] = s[r * 101 + t];
  }
}

// ---------------- kernel 5: GEMM3 -> g_cur3[o][J] ----------------------------
__global__ __launch_bounds__(128) void gemm3_kernel(
    const float* __restrict__ W3, const float* __restrict__ b3) {
  __shared__ float Wsm[10 * 512];
  __shared__ float Xs[64][64];
  int j0 = blockIdx.x * 64;
  int tid = threadIdx.x;
  int jj = tid & 63, og = tid >> 6;      // og in {0,1}
  for (int i = tid; i < 10 * 512; i += 128) {
    int o = i >> 9, k = i & 511;
    Wsm[i] = (k < FH) ? W3[o * FH + k] : 0.f;
  }
  __syncthreads();
  float acc[5] = {0.f, 0.f, 0.f, 0.f, 0.f};
#pragma unroll 1
  for (int k0 = 0; k0 < 512; k0 += 64) {
#pragma unroll
    for (int s = 0; s < 8; s++) {
      int i = tid + s * 128;
      int kk = i >> 4, c4 = i & 15;
      int k = k0 + kk;
      float4 v = make_float4(0.f, 0.f, 0.f, 0.f);
      if (k < FH)
        v = *reinterpret_cast<const float4*>(g_psp3 + (size_t)k * J + j0 + c4 * 4);
      *reinterpret_cast<float4*>(&Xs[kk][c4 * 4]) = v;
    }
    __syncthreads();
#pragma unroll 16
    for (int kk = 0; kk < 64; kk++) {
      float x = Xs[kk][jj];
      int k = k0 + kk;
#pragma unroll
      for (int o = 0; o < 5; o++)
        acc[o] = fmaf(Wsm[(og * 5 + o) * 512 + k], x, acc[o]);
    }
    __syncthreads();
  }
#pragma unroll
  for (int o = 0; o < 5; o++) {
    int oo = og * 5 + o;
    g_cur3[(size_t)oo * J + j0 + jj] = __fadd_rn(acc[o], b3[oo]);
  }
}

// ---------------- kernel 6: LIF layer 3 -> out[b][o][t] ----------------------
__global__ __launch_bounds__(256) void lif3_out_kernel(float* __restrict__ out) {
  __shared__ float s[64 * 101];
  int rid0 = blockIdx.x * 64;     // rid = o*256 + b
  int tid = threadIdx.x;
  for (int i = tid; i < 6400; i += 256) {
    int r = i / 100, t = i - r * 100;
    s[r * 101 + t] = g_cur3[(size_t)rid0 * 100 + i];
  }
  __syncthreads();
  if (tid < 64) {
    int rid = rid0 + tid;
    int o = rid >> 8, b = rid & 255;
    float* po = out + ((size_t)b * 10 + o) * NT;
    const float* row = s + tid * 101;
    float v = 0.f, sp = 0.f;
#pragma unroll
    for (int t = 0; t < NT; t++) {
      v = __fadd_rn(__fmul_rn(__fmul_rn(v, EMC), __fadd_rn(1.0f, -sp)), row[t]);
      sp = (v > 1.0f) ? 1.0f : 0.f;
      po[t] = sp;
    }
  }
}

// ---------------- launcher ---------------------------------------------------
extern "C" void kernel_launch(void* const* d_in, const int* in_sizes, int n_in,
                              void* d_out, int out_size) {
  const float *X = nullptr, *W1 = nullptr, *b1 = nullptr, *W2 = nullptr,
              *b2 = nullptr, *W3 = nullptr, *b3 = nullptr;
  for (int i = 0; i < n_in; i++) {
    switch (in_sizes[i]) {
      case 20070400: X  = (const float*)d_in[i]; break;  // 256*784*100
      case 784000:   W1 = (const float*)d_in[i]; break;  // 1000*784
      case 1000:     b1 = (const float*)d_in[i]; break;
      case 250000:   W2 = (const float*)d_in[i]; break;  // 500*500
      case 500:      b2 = (const float*)d_in[i]; break;
      case 5000:     W3 = (const float*)d_in[i]; break;  // 10*500
      case 10:       b3 = (const float*)d_in[i]; break;
      default: break;
    }
  }
  float* out = (float*)d_out;

  xT_kernel<<<dim3(100, FIN), 256>>>(X);
  w1T_kernel<<<FIN, 256>>>(W1);
  w2T_kernel<<<512, 256>>>(W2);
  gemm1_kernel<<<dim3(16, 200), 128>>>(b1);
  iir_kernel<<<2000, 256>>>();
  gemm2_kernel<<<dim3(8, 200), 128>>>(b2);
  lifiir_kernel<<<2000, 256>>>();
  gemm3_kernel<<<400, 128>>>(W3, b3);
  lif3_out_kernel<<<40, 256>>>(out);
}

// round 14
// speedup vs baseline: 1.1367x; 1.1367x over previous
#include <cuda_runtime.h>
#include <cstdint>
#include <cstddef>

#define NB 256
#define FIN 784
#define FH 500
#define NT 100
#define J 25600                 /* NB*NT flattened column dim */
#define NELEM (FH*J)            /* 12,800,000 */

#define EMC 0.7788007830714049f
#define A1C 1.1466802242428472f
#define A2C (-0.2865047968601901f)

// ---------------- scratch (device globals) -----------------------------------
__device__ float g_xT[FIN * J];    // X transposed to [f][J]
__device__ float g_w1T[FIN * 1024];// W1 transposed [k][c], c: 0..499 mu row c,
                                   // 500..999 lv row c-500, 1000..1023 zero
__device__ float g_w2T[512 * 512]; // W2 transposed [k][f], zero-padded
__device__ float g_psp2[NELEM];    // coding -> (IIR in place) psp2, [f][J]
__device__ float g_cur2[NELEM];    // [f][J]
__device__ float g_psp3[NELEM];    // [f][J]
__device__ float g_cur3[10 * J];   // [o][J]

// ---------------- cp.async helpers -------------------------------------------
__device__ __forceinline__ uint32_t smem_u32(const void* p) {
  return (uint32_t)__cvta_generic_to_shared(p);
}
__device__ __forceinline__ void cp_async16(uint32_t s, const void* g) {
  asm volatile("cp.async.cg.shared.global [%0], [%1], 16;" :: "r"(s), "l"(g));
}
__device__ __forceinline__ void cp_async16z(uint32_t s, const void* g, bool p) {
  int sz = p ? 16 : 0;
  asm volatile("cp.async.cg.shared.global [%0], [%1], 16, %2;"
               :: "r"(s), "l"(g), "r"(sz));
}
#define CP_COMMIT() asm volatile("cp.async.commit_group;")
#define CP_WAIT0()  asm volatile("cp.async.wait_group 0;" ::: "memory")
#define CP_WAIT1()  asm volatile("cp.async.wait_group 1;" ::: "memory")

// ---------------- packed fp32x2 FMA (Blackwell FFMA2) ------------------------
__device__ __forceinline__ unsigned long long pack2(float a) {
  unsigned long long d;
  asm("mov.b64 %0, {%1, %1};" : "=l"(d) : "f"(a));
  return d;
}
__device__ __forceinline__ void fma2(unsigned long long& d,
                                     unsigned long long a,
                                     unsigned long long b) {
  asm("fma.rn.f32x2 %0, %1, %2, %3;" : "=l"(d) : "l"(a), "l"(b), "l"(d));
}
__device__ __forceinline__ float2 unpack2(unsigned long long v) {
  float lo, hi;
  asm("mov.b64 {%0, %1}, %2;" : "=f"(lo), "=f"(hi) : "l"(v));
  return make_float2(lo, hi);
}

// ---------------- JAX threefry-2x32, key = (0, 42) ---------------------------
__device__ __forceinline__ uint32_t rotl32(uint32_t v, int d) {
  return (v << d) | (v >> (32 - d));
}

__device__ __forceinline__ void threefry_0_42(uint32_t x0, uint32_t x1,
                                              uint32_t& o0, uint32_t& o1) {
  const uint32_t ks1 = 42u;
  const uint32_t ks2 = 0x1BD11BDAu ^ 42u;
  x1 += ks1;
#define TF_R(d) { x0 += x1; x1 = rotl32(x1, d); x1 ^= x0; }
  TF_R(13) TF_R(15) TF_R(26) TF_R(6)
  x0 += ks1; x1 += ks2 + 1u;
  TF_R(17) TF_R(29) TF_R(16) TF_R(24)
  x0 += ks2; x1 += 2u;
  TF_R(13) TF_R(15) TF_R(26) TF_R(6)
  x0 += 0u; x1 += ks1 + 3u;
  TF_R(17) TF_R(29) TF_R(16) TF_R(24)
  x0 += ks1; x1 += ks2 + 4u;
  TF_R(13) TF_R(15) TF_R(26) TF_R(6)
  x0 += ks2; x1 += 5u;
#undef TF_R
  o0 = x0; o1 = x1;
}

__device__ __forceinline__ float erfinv_xla(float x) {
  float nx2 = __fmul_rn(x, x);
  float w = -log1pf(-nx2);
  float p;
  if (w < 5.0f) {
    w = __fadd_rn(w, -2.5f);
    p = 2.81022636e-08f;
    p = __fadd_rn(3.43273939e-07f, __fmul_rn(p, w));
    p = __fadd_rn(-3.5233877e-06f, __fmul_rn(p, w));
    p = __fadd_rn(-4.39150654e-06f, __fmul_rn(p, w));
    p = __fadd_rn(0.00021858087f, __fmul_rn(p, w));
    p = __fadd_rn(-0.00125372503f, __fmul_rn(p, w));
    p = __fadd_rn(-0.00417768164f, __fmul_rn(p, w));
    p = __fadd_rn(0.246640727f, __fmul_rn(p, w));
    p = __fadd_rn(1.50140941f, __fmul_rn(p, w));
  } else {
    w = __fadd_rn(sqrtf(w), -3.0f);
    p = -0.000200214257f;
    p = __fadd_rn(0.000100950558f, __fmul_rn(p, w));
    p = __fadd_rn(0.00134934322f, __fmul_rn(p, w));
    p = __fadd_rn(-0.00367342844f, __fmul_rn(p, w));
    p = __fadd_rn(0.00573950773f, __fmul_rn(p, w));
    p = __fadd_rn(-0.0076224613f, __fmul_rn(p, w));
    p = __fadd_rn(0.00943887047f, __fmul_rn(p, w));
    p = __fadd_rn(1.00167406f, __fmul_rn(p, w));
    p = __fadd_rn(2.83297682f, __fmul_rn(p, w));
  }
  return __fmul_rn(p, x);
}

__device__ __forceinline__ float eps_at(uint32_t ctr) {
  uint32_t r0, r1;
  threefry_0_42(0u, ctr, r0, r1);
  uint32_t bits = r0 ^ r1;
  const float lo = -0.99999994039535522461f;
  float f = __fadd_rn(__uint_as_float((bits >> 9) | 0x3f800000u), -1.0f);
  float u = __fadd_rn(__fmul_rn(f, 2.0f), lo);
  u = fmaxf(u, lo);
  return __fmul_rn(1.4142135623730951f, erfinv_xla(u));
}

// ---------------- kernel 0a: transpose X -> g_xT[f][J] -----------------------
__global__ __launch_bounds__(256) void xT_kernel(const float* __restrict__ X) {
  int f = blockIdx.y;
  int j = blockIdx.x * 256 + threadIdx.x;
  int b = j / NT, t = j - b * NT;
  g_xT[(size_t)f * J + j] = X[(size_t)b * (FIN * NT) + f * NT + t];
}

// ---------------- kernel 0b: transpose W1 -> g_w1T[k][1024] ------------------
__global__ __launch_bounds__(256) void w1T_kernel(const float* __restrict__ W1) {
  int k = blockIdx.x;
  for (int c = threadIdx.x; c < 1024; c += 256)
    g_w1T[(size_t)k * 1024 + c] = (c < 1000) ? W1[(size_t)c * FIN + k] : 0.f;
}

// ---------------- kernel 0c: transpose W2 -> g_w2T[512][512] -----------------
__global__ __launch_bounds__(256) void w2T_kernel(const float* __restrict__ W2) {
  int k = blockIdx.x;
  for (int c = threadIdx.x; c < 512; c += 256)
    g_w2T[(size_t)k * 512 + c] =
        (c < FH && k < FH) ? W2[(size_t)c * FH + k] : 0.f;
}

// ---------------- kernel 1: GEMM1 + relu + coding(+eps) -> g_psp2[f][J] ------
// Block tile: 64 M-rows (32 mu + 32 lv) x 128 j. 128 threads, 8x8 thread tile.
// 3-stage cp.async pipeline: at iter c, issue chunk c+2, compute c, wait c+1.
__global__ __launch_bounds__(128, 4) void gemm1_kernel(
    const float* __restrict__ b1) {
  __shared__ float Xs[3][16][128];
  __shared__ float Ws[3][16][68];
  int f0 = blockIdx.x * 32;
  int j0 = blockIdx.y * 128;
  int tid = threadIdx.x;
  int tx = tid & 15, ty = tid >> 4;      // ty 0..7 -> 4 f rows each

  int kk_s = tid >> 3;                   // 0..15
  int q8   = tid & 7;                    // 0..7
  const float* xsrc = g_xT + j0 + q8 * 4;
  const float* wsrc = g_w1T + f0 + q8 * 4;

  unsigned long long acc2[8][4];
#pragma unroll
  for (int i = 0; i < 8; i++)
#pragma unroll
    for (int p = 0; p < 4; p++) acc2[i][p] = 0ull;

  const int NCH = FIN / 16;              // 49 exact chunks

#define G1_STAGE(buf, ch)                                                     \
  {                                                                           \
    int k0_ = (ch) * 16;                                                      \
    _Pragma("unroll")                                                         \
    for (int s = 0; s < 4; s++)                                               \
      cp_async16(smem_u32(&Xs[buf][kk_s][q8 * 4 + s * 32]),                   \
                 xsrc + (size_t)(k0_ + kk_s) * J + s * 32);                   \
    cp_async16(smem_u32(&Ws[buf][kk_s][q8 * 4]),                              \
               wsrc + (size_t)(k0_ + kk_s) * 1024);                           \
    cp_async16(smem_u32(&Ws[buf][kk_s][32 + q8 * 4]),                         \
               wsrc + (size_t)(k0_ + kk_s) * 1024 + 500);                     \
  }

  // prologue: chunks 0 and 1 in flight, wait for 0
  G1_STAGE(0, 0) CP_COMMIT();
  G1_STAGE(1, 1) CP_COMMIT();
  CP_WAIT1();
  __syncthreads();

#pragma unroll 1
  for (int c = 0; c < NCH; c++) {
    int cur = c % 3;
    bool issue = (c + 2 < NCH);
    if (issue) {
      G1_STAGE((c + 2) % 3, c + 2)
      CP_COMMIT();
    }
#pragma unroll
    for (int kk = 0; kk < 16; kk++) {
      float4 a0 = *reinterpret_cast<const float4*>(&Ws[cur][kk][ty * 4]);       // mu
      float4 a1 = *reinterpret_cast<const float4*>(&Ws[cur][kk][32 + ty * 4]);  // lv
      ulonglong2 bq0 = *reinterpret_cast<const ulonglong2*>(&Xs[cur][kk][tx * 4]);
      ulonglong2 bq1 = *reinterpret_cast<const ulonglong2*>(&Xs[cur][kk][tx * 4 + 64]);
      unsigned long long bp[4] = {bq0.x, bq0.y, bq1.x, bq1.y};
      float av[8] = {a0.x, a0.y, a0.z, a0.w, a1.x, a1.y, a1.z, a1.w};
#pragma unroll
      for (int i = 0; i < 8; i++) {
        unsigned long long ap = pack2(av[i]);
#pragma unroll
        for (int p = 0; p < 4; p++) fma2(acc2[i][p], ap, bp[p]);
      }
    }
    if (c + 1 < NCH) {
      if (issue) { CP_WAIT1(); } else { CP_WAIT0(); }
      __syncthreads();
    }
  }
#undef G1_STAGE

  // epilogue: acc2[i] (i<4) = mu row f0+ty*4+i; acc2[i+4] = paired lnvar row.
#pragma unroll
  for (int i = 0; i < 4; i++) {
    int f = f0 + ty * 4 + i;
    if (f >= FH) continue;
    float bm = b1[f], bl = b1[f + FH];
#pragma unroll
    for (int h = 0; h < 2; h++) {
      int jb = j0 + h * 64 + tx * 4;
      float2 m0 = unpack2(acc2[i][h * 2]);
      float2 m1 = unpack2(acc2[i][h * 2 + 1]);
      float2 l0 = unpack2(acc2[i + 4][h * 2]);
      float2 l1 = unpack2(acc2[i + 4][h * 2 + 1]);
      float am[4] = {m0.x, m0.y, m1.x, m1.y};
      float al[4] = {l0.x, l0.y, l1.x, l1.y};
      float o[4];
#pragma unroll
      for (int r = 0; r < 4; r++) {
        int j = jb + r;
        int b = j / NT, t = j - b * NT;
        float mu = fmaxf(__fadd_rn(am[r], bm), 0.f);
        float lv = fmaxf(__fadd_rn(al[r], bl), 0.f);
        float sg = expf(__fmul_rn(0.5f, lv));
        float ev = eps_at((uint32_t)b * 50000u + (uint32_t)f * 100u + (uint32_t)t);
        o[r] = __fadd_rn(mu, __fmul_rn(ev, sg));
      }
      *reinterpret_cast<float4*>(g_psp2 + (size_t)f * J + jb) =
          make_float4(o[0], o[1], o[2], o[3]);
    }
  }
}

// ---------------- kernel 2: dual-exp IIR in place on g_psp2 ------------------
__global__ __launch_bounds__(256) void iir_kernel() {
  __shared__ float s[64 * 101];
  size_t row0 = (size_t)blockIdx.x * 64;
  int tid = threadIdx.x;
  for (int i = tid; i < 6400; i += 256) {
    int r = i / 100, t = i - r * 100;
    s[r * 101 + t] = g_psp2[row0 * 100 + i];
  }
  __syncthreads();
  if (tid < 64) {
    float y1 = 0.f, y2 = 0.f;
    float* row = s + tid * 101;
#pragma unroll
    for (int t = 0; t < NT; t++) {
      float y = __fadd_rn(__fadd_rn(__fmul_rn(A1C, y1), __fmul_rn(A2C, y2)),
                          row[t]);
      row[t] = y;
      y2 = y1; y1 = y;
    }
  }
  __syncthreads();
  for (int i = tid; i < 6400; i += 256) {
    int r = i / 100, t = i - r * 100;
    g_psp2[row0 * 100 + i] = s[r * 101 + t];
  }
}

// ---------------- kernel 3: GEMM2 -> g_cur2[f][J] ----------------------------
// Block tile 64f x 128j, 128 threads, 8x8; 3-stage cp.async pipeline.
__global__ __launch_bounds__(128, 4) void gemm2_kernel(
    const float* __restrict__ b2) {
  __shared__ float Xs[3][16][128];
  __shared__ float Ws[3][16][68];
  int f0 = blockIdx.x * 64;
  int j0 = blockIdx.y * 128;
  int tid = threadIdx.x;
  int tx = tid & 15, ty = tid >> 4;

  int kk_s = tid >> 3;                   // 0..15
  int q8   = tid & 7;                    // 0..7
  const float* xsrc = g_psp2 + j0 + q8 * 4;
  const float* wsrc = g_w2T + f0 + q8 * 4;

  unsigned long long acc2[8][4];
#pragma unroll
  for (int i = 0; i < 8; i++)
#pragma unroll
    for (int p = 0; p < 4; p++) acc2[i][p] = 0ull;

  const int NCH = 32;                    // 512 k padded

#define G2_STAGE(buf, ch)                                                     \
  {                                                                           \
    int k0_ = (ch) * 16;                                                      \
    bool xp_ = (k0_ + kk_s < FH);                                             \
    _Pragma("unroll")                                                         \
    for (int s = 0; s < 4; s++)                                               \
      cp_async16z(smem_u32(&Xs[buf][kk_s][q8 * 4 + s * 32]),                  \
                  xsrc + (size_t)(k0_ + kk_s) * J + s * 32, xp_);             \
    cp_async16(smem_u32(&Ws[buf][kk_s][q8 * 4]),                              \
               wsrc + (size_t)(k0_ + kk_s) * 512);                            \
    cp_async16(smem_u32(&Ws[buf][kk_s][32 + q8 * 4]),                         \
               wsrc + (size_t)(k0_ + kk_s) * 512 + 32);                       \
  }

  G2_STAGE(0, 0) CP_COMMIT();
  G2_STAGE(1, 1) CP_COMMIT();
  CP_WAIT1();
  __syncthreads();

#pragma unroll 1
  for (int c = 0; c < NCH; c++) {
    int cur = c % 3;
    bool issue = (c + 2 < NCH);
    if (issue) {
      G2_STAGE((c + 2) % 3, c + 2)
      CP_COMMIT();
    }
#pragma unroll
    for (int kk = 0; kk < 16; kk++) {
      float4 a0 = *reinterpret_cast<const float4*>(&Ws[cur][kk][ty * 4]);
      float4 a1 = *reinterpret_cast<const float4*>(&Ws[cur][kk][32 + ty * 4]);
      ulonglong2 bq0 = *reinterpret_cast<const ulonglong2*>(&Xs[cur][kk][tx * 4]);
      ulonglong2 bq1 = *reinterpret_cast<const ulonglong2*>(&Xs[cur][kk][tx * 4 + 64]);
      unsigned long long bp[4] = {bq0.x, bq0.y, bq1.x, bq1.y};
      float av[8] = {a0.x, a0.y, a0.z, a0.w, a1.x, a1.y, a1.z, a1.w};
#pragma unroll
      for (int i = 0; i < 8; i++) {
        unsigned long long ap = pack2(av[i]);
#pragma unroll
        for (int p = 0; p < 4; p++) fma2(acc2[i][p], ap, bp[p]);
      }
    }
    if (c + 1 < NCH) {
      if (issue) { CP_WAIT1(); } else { CP_WAIT0(); }
      __syncthreads();
    }
  }
#undef G2_STAGE

#pragma unroll
  for (int i = 0; i < 8; i++) {
    int f = f0 + ((i < 4) ? (ty * 4 + i) : (32 + ty * 4 + i - 4));
    if (f >= FH) continue;
    float bb = b2[f];
#pragma unroll
    for (int h = 0; h < 2; h++) {
      int jb = j0 + h * 64 + tx * 4;
      float2 c0 = unpack2(acc2[i][h * 2]);
      float2 c1 = unpack2(acc2[i][h * 2 + 1]);
      float ac[4] = {c0.x, c0.y, c1.x, c1.y};
      float o[4];
#pragma unroll
      for (int r = 0; r < 4; r++)
        o[r] = __fadd_rn(ac[r], bb);
      *reinterpret_cast<float4*>(g_cur2 + (size_t)f * J + jb) =
          make_float4(o[0], o[1], o[2], o[3]);
    }
  }
}

// ---------------- kernel 4: LIF + second IIR: g_cur2 -> g_psp3 ---------------
__global__ __launch_bounds__(256) void lifiir_kernel() {
  __shared__ float s[64 * 101];
  size_t row0 = (size_t)blockIdx.x * 64;
  int tid = threadIdx.x;
  for (int i = tid; i < 6400; i += 256) {
    int r = i / 100, t = i - r * 100;
    s[r * 101 + t] = g_cur2[row0 * 100 + i];
  }
  __syncthreads();
  if (tid < 64) {
    float v = 0.f, sp = 0.f, y1 = 0.f, y2 = 0.f;
    float* row = s + tid * 101;
#pragma unroll
    for (int t = 0; t < NT; t++) {
      v = __fadd_rn(__fmul_rn(__fmul_rn(v, EMC), __fadd_rn(1.0f, -sp)), row[t]);
      sp = (v > 1.0f) ? 1.0f : 0.f;
      float y = __fadd_rn(__fadd_rn(__fmul_rn(A1C, y1), __fmul_rn(A2C, y2)), sp);
      row[t] = y;
      y2 = y1; y1 = y;
    }
  }
  __syncthreads();
  for (int i = tid; i < 6400; i += 256) {
    int r = i / 100, t = i - r * 100;
    g_psp3[row0 * 100 + i] = s[r * 101 + t];
  }
}

// ---------------- kernel 5: GEMM3 -> g_cur3[o][J] ----------------------------
__global__ __launch_bounds__(128) void gemm3_kernel(
    const float* __restrict__ W3, const float* __restrict__ b3) {
  __shared__ float Wsm[10 * 512];
  __shared__ float Xs[64][64];
  int j0 = blockIdx.x * 64;
  int tid = threadIdx.x;
  int jj = tid & 63, og = tid >> 6;      // og in {0,1}
  for (int i = tid; i < 10 * 512; i += 128) {
    int o = i >> 9, k = i & 511;
    Wsm[i] = (k < FH) ? W3[o * FH + k] : 0.f;
  }
  __syncthreads();
  float acc[5] = {0.f, 0.f, 0.f, 0.f, 0.f};
#pragma unroll 1
  for (int k0 = 0; k0 < 512; k0 += 64) {
#pragma unroll
    for (int s = 0; s < 8; s++) {
      int i = tid + s * 128;
      int kk = i >> 4, c4 = i & 15;
      int k = k0 + kk;
      float4 v = make_float4(0.f, 0.f, 0.f, 0.f);
      if (k < FH)
        v = *reinterpret_cast<const float4*>(g_psp3 + (size_t)k * J + j0 + c4 * 4);
      *reinterpret_cast<float4*>(&Xs[kk][c4 * 4]) = v;
    }
    __syncthreads();
#pragma unroll 16
    for (int kk = 0; kk < 64; kk++) {
      float x = Xs[kk][jj];
      int k = k0 + kk;
#pragma unroll
      for (int o = 0; o < 5; o++)
        acc[o] = fmaf(Wsm[(og * 5 + o) * 512 + k], x, acc[o]);
    }
    __syncthreads();
  }
#pragma unroll
  for (int o = 0; o < 5; o++) {
    int oo = og * 5 + o;
    g_cur3[(size_t)oo * J + j0 + jj] = __fadd_rn(acc[o], b3[oo]);
  }
}

// ---------------- kernel 6: LIF layer 3 -> out[b][o][t] ----------------------
__global__ __launch_bounds__(256) void lif3_out_kernel(float* __restrict__ out) {
  __shared__ float s[64 * 101];
  int rid0 = blockIdx.x * 64;     // rid = o*256 + b
  int tid = threadIdx.x;
  for (int i = tid; i < 6400; i += 256) {
    int r = i / 100, t = i - r * 100;
    s[r * 101 + t] = g_cur3[(size_t)rid0 * 100 + i];
  }
  __syncthreads();
  if (tid < 64) {
    int rid = rid0 + tid;
    int o = rid >> 8, b = rid & 255;
    float* po = out + ((size_t)b * 10 + o) * NT;
    const float* row = s + tid * 101;
    float v = 0.f, sp = 0.f;
#pragma unroll
    for (int t = 0; t < NT; t++) {
      v = __fadd_rn(__fmul_rn(__fmul_rn(v, EMC), __fadd_rn(1.0f, -sp)), row[t]);
      sp = (v > 1.0f) ? 1.0f : 0.f;
      po[t] = sp;
    }
  }
}

// ---------------- launcher ---------------------------------------------------
extern "C" void kernel_launch(void* const* d_in, const int* in_sizes, int n_in,
                              void* d_out, int out_size) {
  const float *X = nullptr, *W1 = nullptr, *b1 = nullptr, *W2 = nullptr,
              *b2 = nullptr, *W3 = nullptr, *b3 = nullptr;
  for (int i = 0; i < n_in; i++) {
    switch (in_sizes[i]) {
      case 20070400: X  = (const float*)d_in[i]; break;  // 256*784*100
      case 784000:   W1 = (const float*)d_in[i]; break;  // 1000*784
      case 1000:     b1 = (const float*)d_in[i]; break;
      case 250000:   W2 = (const float*)d_in[i]; break;  // 500*500
      case 500:      b2 = (const float*)d_in[i]; break;
      case 5000:     W3 = (const float*)d_in[i]; break;  // 10*500
      case 10:       b3 = (const float*)d_in[i]; break;
      default: break;
    }
  }
  float* out = (float*)d_out;

  xT_kernel<<<dim3(100, FIN), 256>>>(X);
  w1T_kernel<<<FIN, 256>>>(W1);
  w2T_kernel<<<512, 256>>>(W2);
  gemm1_kernel<<<dim3(16, 200), 128>>>(b1);
  iir_kernel<<<2000, 256>>>();
  gemm2_kernel<<<dim3(8, 200), 128>>>(b2);
  lifiir_kernel<<<2000, 256>>>();
  gemm3_kernel<<<400, 128>>>(W3, b3);
  lif3_out_kernel<<<40, 256>>>(out);
}

// round 16
// speedup vs baseline: 1.1637x; 1.0237x over previous
#include <cuda_runtime.h>
#include <cstdint>
#include <cstddef>

#define NB 256
#define FIN 784
#define FH 500
#define NT 100
#define J 25600                 /* NB*NT flattened column dim */
#define NELEM (FH*J)            /* 12,800,000 */

#define EMC 0.7788007830714049f
#define A1C 1.1466802242428472f
#define A2C (-0.2865047968601901f)

// ---------------- scratch (device globals) -----------------------------------
__device__ float g_xT[FIN * J];    // X transposed to [f][J]
__device__ float g_w1T[FIN * 1024];// W1 transposed [k][c], c: 0..499 mu row c,
                                   // 500..999 lv row c-500, 1000..1023 zero
__device__ float g_w2T[512 * 512]; // W2 transposed [k][f], zero-padded
__device__ float g_psp2[NELEM];    // coding -> (IIR in place) psp2, [f][J]
__device__ float g_cur2[NELEM];    // [f][J]
__device__ float g_psp3[NELEM];    // [f][J]
__device__ float g_cur3[10 * J];   // [o][J]

// ---------------- cp.async helpers -------------------------------------------
__device__ __forceinline__ uint32_t smem_u32(const void* p) {
  return (uint32_t)__cvta_generic_to_shared(p);
}
__device__ __forceinline__ void cp_async16(uint32_t s, const void* g) {
  asm volatile("cp.async.cg.shared.global [%0], [%1], 16;" :: "r"(s), "l"(g));
}
__device__ __forceinline__ void cp_async16z(uint32_t s, const void* g, bool p) {
  int sz = p ? 16 : 0;
  asm volatile("cp.async.cg.shared.global [%0], [%1], 16, %2;"
               :: "r"(s), "l"(g), "r"(sz));
}
#define CP_COMMIT() asm volatile("cp.async.commit_group;")
#define CP_WAIT0()  asm volatile("cp.async.wait_group 0;" ::: "memory")

// ---------------- packed fp32x2 FMA (Blackwell FFMA2) ------------------------
__device__ __forceinline__ unsigned long long pack2(float a) {
  unsigned long long d;
  asm("mov.b64 %0, {%1, %1};" : "=l"(d) : "f"(a));
  return d;
}
__device__ __forceinline__ void fma2(unsigned long long& d,
                                     unsigned long long a,
                                     unsigned long long b) {
  asm("fma.rn.f32x2 %0, %1, %2, %3;" : "=l"(d) : "l"(a), "l"(b), "l"(d));
}
__device__ __forceinline__ float2 unpack2(unsigned long long v) {
  float lo, hi;
  asm("mov.b64 {%0, %1}, %2;" : "=f"(lo), "=f"(hi) : "l"(v));
  return make_float2(lo, hi);
}

// ---------------- JAX threefry-2x32, key = (0, 42) ---------------------------
__device__ __forceinline__ uint32_t rotl32(uint32_t v, int d) {
  return (v << d) | (v >> (32 - d));
}

__device__ __forceinline__ void threefry_0_42(uint32_t x0, uint32_t x1,
                                              uint32_t& o0, uint32_t& o1) {
  const uint32_t ks1 = 42u;
  const uint32_t ks2 = 0x1BD11BDAu ^ 42u;
  x1 += ks1;
#define TF_R(d) { x0 += x1; x1 = rotl32(x1, d); x1 ^= x0; }
  TF_R(13) TF_R(15) TF_R(26) TF_R(6)
  x0 += ks1; x1 += ks2 + 1u;
  TF_R(17) TF_R(29) TF_R(16) TF_R(24)
  x0 += ks2; x1 += 2u;
  TF_R(13) TF_R(15) TF_R(26) TF_R(6)
  x0 += 0u; x1 += ks1 + 3u;
  TF_R(17) TF_R(29) TF_R(16) TF_R(24)
  x0 += ks1; x1 += ks2 + 4u;
  TF_R(13) TF_R(15) TF_R(26) TF_R(6)
  x0 += ks2; x1 += 5u;
#undef TF_R
  o0 = x0; o1 = x1;
}

__device__ __forceinline__ float erfinv_xla(float x) {
  float nx2 = __fmul_rn(x, x);
  float w = -log1pf(-nx2);
  float p;
  if (w < 5.0f) {
    w = __fadd_rn(w, -2.5f);
    p = 2.81022636e-08f;
    p = __fadd_rn(3.43273939e-07f, __fmul_rn(p, w));
    p = __fadd_rn(-3.5233877e-06f, __fmul_rn(p, w));
    p = __fadd_rn(-4.39150654e-06f, __fmul_rn(p, w));
    p = __fadd_rn(0.00021858087f, __fmul_rn(p, w));
    p = __fadd_rn(-0.00125372503f, __fmul_rn(p, w));
    p = __fadd_rn(-0.00417768164f, __fmul_rn(p, w));
    p = __fadd_rn(0.246640727f, __fmul_rn(p, w));
    p = __fadd_rn(1.50140941f, __fmul_rn(p, w));
  } else {
    w = __fadd_rn(sqrtf(w), -3.0f);
    p = -0.000200214257f;
    p = __fadd_rn(0.000100950558f, __fmul_rn(p, w));
    p = __fadd_rn(0.00134934322f, __fmul_rn(p, w));
    p = __fadd_rn(-0.00367342844f, __fmul_rn(p, w));
    p = __fadd_rn(0.00573950773f, __fmul_rn(p, w));
    p = __fadd_rn(-0.0076224613f, __fmul_rn(p, w));
    p = __fadd_rn(0.00943887047f, __fmul_rn(p, w));
    p = __fadd_rn(1.00167406f, __fmul_rn(p, w));
    p = __fadd_rn(2.83297682f, __fmul_rn(p, w));
  }
  return __fmul_rn(p, x);
}

__device__ __forceinline__ float eps_at(uint32_t ctr) {
  uint32_t r0, r1;
  threefry_0_42(0u, ctr, r0, r1);
  uint32_t bits = r0 ^ r1;
  const float lo = -0.99999994039535522461f;
  float f = __fadd_rn(__uint_as_float((bits >> 9) | 0x3f800000u), -1.0f);
  float u = __fadd_rn(__fmul_rn(f, 2.0f), lo);
  u = fmaxf(u, lo);
  return __fmul_rn(1.4142135623730951f, erfinv_xla(u));
}

// ---------------- kernel 0a: transpose X -> g_xT[f][J] -----------------------
__global__ __launch_bounds__(256) void xT_kernel(const float* __restrict__ X) {
  int f = blockIdx.y;
  int j = blockIdx.x * 256 + threadIdx.x;
  int b = j / NT, t = j - b * NT;
  g_xT[(size_t)f * J + j] = X[(size_t)b * (FIN * NT) + f * NT + t];
}

// ---------------- kernel 0b: transpose W1 -> g_w1T[k][1024] ------------------
__global__ __launch_bounds__(256) void w1T_kernel(const float* __restrict__ W1) {
  int k = blockIdx.x;
  for (int c = threadIdx.x; c < 1024; c += 256)
    g_w1T[(size_t)k * 1024 + c] = (c < 1000) ? W1[(size_t)c * FIN + k] : 0.f;
}

// ---------------- kernel 0c: transpose W2 -> g_w2T[512][512] -----------------
__global__ __launch_bounds__(256) void w2T_kernel(const float* __restrict__ W2) {
  int k = blockIdx.x;
  for (int c = threadIdx.x; c < 512; c += 256)
    g_w2T[(size_t)k * 512 + c] =
        (c < FH && k < FH) ? W2[(size_t)c * FH + k] : 0.f;
}

// ---------------- kernel 1: GEMM1 + relu + coding(+eps) -> g_psp2[f][J] ------
// Block tile: 64 M-rows (32 mu + 32 lv) x 128 j. 128 threads, 8x8 thread tile.
// 2-stage cp.async double buffering (round-12 structure). eps values are
// computed DURING the mainloop (1 per k-chunk, c<32) into smem, hiding the
// ~120-instr hash chain under the fma-bound chunks; epilogue just reads them.
__global__ __launch_bounds__(128, 4) void gemm1_kernel(
    const float* __restrict__ b1) {
  __shared__ float Xs[2][16][128];
  __shared__ float Ws[2][16][68];
  __shared__ float s_eps[32 * 128];      // [c][tid]
  int f0 = blockIdx.x * 32;
  int j0 = blockIdx.y * 128;
  int tid = threadIdx.x;
  int tx = tid & 15, ty = tid >> 4;      // ty 0..7 -> 4 f rows each

  int kk_s = tid >> 3;                   // 0..15
  int q8   = tid & 7;                    // 0..7
  const float* xsrc = g_xT + j0 + q8 * 4;
  const float* wsrc = g_w1T + f0 + q8 * 4;

  unsigned long long acc2[8][4];
#pragma unroll
  for (int i = 0; i < 8; i++)
#pragma unroll
    for (int p = 0; p < 4; p++) acc2[i][p] = 0ull;

  const int NCH = FIN / 16;              // 49 exact chunks

  // prologue: chunk 0 into buffer 0
#pragma unroll
  for (int s = 0; s < 4; s++)
    cp_async16(smem_u32(&Xs[0][kk_s][q8 * 4 + s * 32]),
               xsrc + (size_t)kk_s * J + s * 32);
  cp_async16(smem_u32(&Ws[0][kk_s][q8 * 4]),
             wsrc + (size_t)kk_s * 1024);
  cp_async16(smem_u32(&Ws[0][kk_s][32 + q8 * 4]),
             wsrc + (size_t)kk_s * 1024 + 500);
  CP_COMMIT();
  CP_WAIT0();
  __syncthreads();

#pragma unroll 1
  for (int c = 0; c < NCH; c++) {
    int cur = c & 1;
    bool more = (c + 1 < NCH);
    if (more) {
      int k0 = (c + 1) * 16;
#pragma unroll
      for (int s = 0; s < 4; s++)
        cp_async16(smem_u32(&Xs[cur ^ 1][kk_s][q8 * 4 + s * 32]),
                   xsrc + (size_t)(k0 + kk_s) * J + s * 32);
      cp_async16(smem_u32(&Ws[cur ^ 1][kk_s][q8 * 4]),
                 wsrc + (size_t)(k0 + kk_s) * 1024);
      cp_async16(smem_u32(&Ws[cur ^ 1][kk_s][32 + q8 * 4]),
                 wsrc + (size_t)(k0 + kk_s) * 1024 + 500);
      CP_COMMIT();
    }
    // one eps element per chunk for the first 32 chunks — hides the hash
    // chain under the fma-bound compute below (ALU/issue slots are idle).
    if (c < 32) {
      int ei = c >> 3, eh = (c >> 2) & 1, er = c & 3;
      int f = f0 + ty * 4 + ei;
      int j = j0 + eh * 64 + tx * 4 + er;
      int b = j / NT, t = j - b * NT;
      float ev = 0.f;
      if (f < FH)
        ev = eps_at((uint32_t)b * 50000u + (uint32_t)f * 100u + (uint32_t)t);
      s_eps[c * 128 + tid] = ev;
    }
#pragma unroll
    for (int kk = 0; kk < 16; kk++) {
      float4 a0 = *reinterpret_cast<const float4*>(&Ws[cur][kk][ty * 4]);       // mu
      float4 a1 = *reinterpret_cast<const float4*>(&Ws[cur][kk][32 + ty * 4]);  // lv
      ulonglong2 bq0 = *reinterpret_cast<const ulonglong2*>(&Xs[cur][kk][tx * 4]);
      ulonglong2 bq1 = *reinterpret_cast<const ulonglong2*>(&Xs[cur][kk][tx * 4 + 64]);
      unsigned long long bp[4] = {bq0.x, bq0.y, bq1.x, bq1.y};
      float av[8] = {a0.x, a0.y, a0.z, a0.w, a1.x, a1.y, a1.z, a1.w};
#pragma unroll
      for (int i = 0; i < 8; i++) {
        unsigned long long ap = pack2(av[i]);
#pragma unroll
        for (int p = 0; p < 4; p++) fma2(acc2[i][p], ap, bp[p]);
      }
    }
    if (more) {
      CP_WAIT0();
      __syncthreads();
    }
  }

  // epilogue: acc2[i] (i<4) = mu row f0+ty*4+i; acc2[i+4] = paired lnvar row.
  // eps already in s_eps (written by this same thread — no sync needed).
#pragma unroll
  for (int i = 0; i < 4; i++) {
    int f = f0 + ty * 4 + i;
    if (f >= FH) continue;
    float bm = b1[f], bl = b1[f + FH];
#pragma unroll
    for (int h = 0; h < 2; h++) {
      int jb = j0 + h * 64 + tx * 4;
      float2 m0 = unpack2(acc2[i][h * 2]);
      float2 m1 = unpack2(acc2[i][h * 2 + 1]);
      float2 l0 = unpack2(acc2[i + 4][h * 2]);
      float2 l1 = unpack2(acc2[i + 4][h * 2 + 1]);
      float am[4] = {m0.x, m0.y, m1.x, m1.y};
      float al[4] = {l0.x, l0.y, l1.x, l1.y};
      float o[4];
#pragma unroll
      for (int r = 0; r < 4; r++) {
        float mu = fmaxf(__fadd_rn(am[r], bm), 0.f);
        float lv = fmaxf(__fadd_rn(al[r], bl), 0.f);
        float sg = expf(__fmul_rn(0.5f, lv));
        float ev = s_eps[(i * 8 + h * 4 + r) * 128 + tid];
        o[r] = __fadd_rn(mu, __fmul_rn(ev, sg));
      }
      *reinterpret_cast<float4*>(g_psp2 + (size_t)f * J + jb) =
          make_float4(o[0], o[1], o[2], o[3]);
    }
  }
}

// ---------------- kernel 2: dual-exp IIR in place on g_psp2 ------------------
__global__ __launch_bounds__(256) void iir_kernel() {
  __shared__ float s[64 * 101];
  size_t row0 = (size_t)blockIdx.x * 64;
  int tid = threadIdx.x;
  for (int i = tid; i < 6400; i += 256) {
    int r = i / 100, t = i - r * 100;
    s[r * 101 + t] = g_psp2[row0 * 100 + i];
  }
  __syncthreads();
  if (tid < 64) {
    float y1 = 0.f, y2 = 0.f;
    float* row = s + tid * 101;
#pragma unroll
    for (int t = 0; t < NT; t++) {
      float y = __fadd_rn(__fadd_rn(__fmul_rn(A1C, y1), __fmul_rn(A2C, y2)),
                          row[t]);
      row[t] = y;
      y2 = y1; y1 = y;
    }
  }
  __syncthreads();
  for (int i = tid; i < 6400; i += 256) {
    int r = i / 100, t = i - r * 100;
    g_psp2[row0 * 100 + i] = s[r * 101 + t];
  }
}

// ---------------- kernel 3: GEMM2 -> g_cur2[f][J] ----------------------------
// Block tile 64f x 128j, 128 threads, 8x8; round-12 2-stage pipeline.
__global__ __launch_bounds__(128, 4) void gemm2_kernel(
    const float* __restrict__ b2) {
  __shared__ float Xs[2][16][128];
  __shared__ float Ws[2][16][68];
  int f0 = blockIdx.x * 64;
  int j0 = blockIdx.y * 128;
  int tid = threadIdx.x;
  int tx = tid & 15, ty = tid >> 4;

  int kk_s = tid >> 3;                   // 0..15
  int q8   = tid & 7;                    // 0..7
  const float* xsrc = g_psp2 + j0 + q8 * 4;
  const float* wsrc = g_w2T + f0 + q8 * 4;

  unsigned long long acc2[8][4];
#pragma unroll
  for (int i = 0; i < 8; i++)
#pragma unroll
    for (int p = 0; p < 4; p++) acc2[i][p] = 0ull;

  const int NCH = 32;                    // 512 k padded

  // prologue: chunk 0
  {
    bool xp = (kk_s < FH);
#pragma unroll
    for (int s = 0; s < 4; s++)
      cp_async16z(smem_u32(&Xs[0][kk_s][q8 * 4 + s * 32]),
                  xsrc + (size_t)kk_s * J + s * 32, xp);
    cp_async16(smem_u32(&Ws[0][kk_s][q8 * 4]),
               wsrc + (size_t)kk_s * 512);
    cp_async16(smem_u32(&Ws[0][kk_s][32 + q8 * 4]),
               wsrc + (size_t)kk_s * 512 + 32);
    CP_COMMIT();
    CP_WAIT0();
    __syncthreads();
  }

#pragma unroll 1
  for (int c = 0; c < NCH; c++) {
    int cur = c & 1;
    bool more = (c + 1 < NCH);
    if (more) {
      int k0 = (c + 1) * 16;
      bool xp = (k0 + kk_s < FH);
#pragma unroll
      for (int s = 0; s < 4; s++)
        cp_async16z(smem_u32(&Xs[cur ^ 1][kk_s][q8 * 4 + s * 32]),
                    xsrc + (size_t)(k0 + kk_s) * J + s * 32, xp);
      cp_async16(smem_u32(&Ws[cur ^ 1][kk_s][q8 * 4]),
                 wsrc + (size_t)(k0 + kk_s) * 512);
      cp_async16(smem_u32(&Ws[cur ^ 1][kk_s][32 + q8 * 4]),
                 wsrc + (size_t)(k0 + kk_s) * 512 + 32);
      CP_COMMIT();
    }
#pragma unroll
    for (int kk = 0; kk < 16; kk++) {
      float4 a0 = *reinterpret_cast<const float4*>(&Ws[cur][kk][ty * 4]);
      float4 a1 = *reinterpret_cast<const float4*>(&Ws[cur][kk][32 + ty * 4]);
      ulonglong2 bq0 = *reinterpret_cast<const ulonglong2*>(&Xs[cur][kk][tx * 4]);
      ulonglong2 bq1 = *reinterpret_cast<const ulonglong2*>(&Xs[cur][kk][tx * 4 + 64]);
      unsigned long long bp[4] = {bq0.x, bq0.y, bq1.x, bq1.y};
      float av[8] = {a0.x, a0.y, a0.z, a0.w, a1.x, a1.y, a1.z, a1.w};
#pragma unroll
      for (int i = 0; i < 8; i++) {
        unsigned long long ap = pack2(av[i]);
#pragma unroll
        for (int p = 0; p < 4; p++) fma2(acc2[i][p], ap, bp[p]);
      }
    }
    if (more) {
      CP_WAIT0();
      __syncthreads();
    }
  }

#pragma unroll
  for (int i = 0; i < 8; i++) {
    int f = f0 + ((i < 4) ? (ty * 4 + i) : (32 + ty * 4 + i - 4));
    if (f >= FH) continue;
    float bb = b2[f];
#pragma unroll
    for (int h = 0; h < 2; h++) {
      int jb = j0 + h * 64 + tx * 4;
      float2 c0 = unpack2(acc2[i][h * 2]);
      float2 c1 = unpack2(acc2[i][h * 2 + 1]);
      float ac[4] = {c0.x, c0.y, c1.x, c1.y};
      float o[4];
#pragma unroll
      for (int r = 0; r < 4; r++)
        o[r] = __fadd_rn(ac[r], bb);
      *reinterpret_cast<float4*>(g_cur2 + (size_t)f * J + jb) =
          make_float4(o[0], o[1], o[2], o[3]);
    }
  }
}

// ---------------- kernel 4: LIF + second IIR: g_cur2 -> g_psp3 ---------------
__global__ __launch_bounds__(256) void lifiir_kernel() {
  __shared__ float s[64 * 101];
  size_t row0 = (size_t)blockIdx.x * 64;
  int tid = threadIdx.x;
  for (int i = tid; i < 6400; i += 256) {
    int r = i / 100, t = i - r * 100;
    s[r * 101 + t] = g_cur2[row0 * 100 + i];
  }
  __syncthreads();
  if (tid < 64) {
    float v = 0.f, sp = 0.f, y1 = 0.f, y2 = 0.f;
    float* row = s + tid * 101;
#pragma unroll
    for (int t = 0; t < NT; t++) {
      v = __fadd_rn(__fmul_rn(__fmul_rn(v, EMC), __fadd_rn(1.0f, -sp)), row[t]);
      sp = (v > 1.0f) ? 1.0f : 0.f;
      float y = __fadd_rn(__fadd_rn(__fmul_rn(A1C, y1), __fmul_rn(A2C, y2)), sp);
      row[t] = y;
      y2 = y1; y1 = y;
    }
  }
  __syncthreads();
  for (int i = tid; i < 6400; i += 256) {
    int r = i / 100, t = i - r * 100;
    g_psp3[row0 * 100 + i] = s[r * 101 + t];
  }
}

// ---------------- kernel 5: GEMM3 -> g_cur3[o][J] ----------------------------
__global__ __launch_bounds__(128) void gemm3_kernel(
    const float* __restrict__ W3, const float* __restrict__ b3) {
  __shared__ float Wsm[10 * 512];
  __shared__ float Xs[64][64];
  int j0 = blockIdx.x * 64;
  int tid = threadIdx.x;
  int jj = tid & 63, og = tid >> 6;      // og in {0,1}
  for (int i = tid; i < 10 * 512; i += 128) {
    int o = i >> 9, k = i & 511;
    Wsm[i] = (k < FH) ? W3[o * FH + k] : 0.f;
  }
  __syncthreads();
  float acc[5] = {0.f, 0.f, 0.f, 0.f, 0.f};
#pragma unroll 1
  for (int k0 = 0; k0 < 512; k0 += 64) {
#pragma unroll
    for (int s = 0; s < 8; s++) {
      int i = tid + s * 128;
      int kk = i >> 4, c4 = i & 15;
      int k = k0 + kk;
      float4 v = make_float4(0.f, 0.f, 0.f, 0.f);
      if (k < FH)
        v = *reinterpret_cast<const float4*>(g_psp3 + (size_t)k * J + j0 + c4 * 4);
      *reinterpret_cast<float4*>(&Xs[kk][c4 * 4]) = v;
    }
    __syncthreads();
#pragma unroll 16
    for (int kk = 0; kk < 64; kk++) {
      float x = Xs[kk][jj];
      int k = k0 + kk;
#pragma unroll
      for (int o = 0; o < 5; o++)
        acc[o] = fmaf(Wsm[(og * 5 + o) * 512 + k], x, acc[o]);
    }
    __syncthreads();
  }
#pragma unroll
  for (int o = 0; o < 5; o++) {
    int oo = og * 5 + o;
    g_cur3[(size_t)oo * J + j0 + jj] = __fadd_rn(acc[o], b3[oo]);
  }
}

// ---------------- kernel 6: LIF layer 3 -> out[b][o][t] ----------------------
__global__ __launch_bounds__(256) void lif3_out_kernel(float* __restrict__ out) {
  __shared__ float s[64 * 101];
  int rid0 = blockIdx.x * 64;     // rid = o*256 + b
  int tid = threadIdx.x;
  for (int i = tid; i < 6400; i += 256) {
    int r = i / 100, t = i - r * 100;
    s[r * 101 + t] = g_cur3[(size_t)rid0 * 100 + i];
  }
  __syncthreads();
  if (tid < 64) {
    int rid = rid0 + tid;
    int o = rid >> 8, b = rid & 255;
    float* po = out + ((size_t)b * 10 + o) * NT;
    const float* row = s + tid * 101;
    float v = 0.f, sp = 0.f;
#pragma unroll
    for (int t = 0; t < NT; t++) {
      v = __fadd_rn(__fmul_rn(__fmul_rn(v, EMC), __fadd_rn(1.0f, -sp)), row[t]);
      sp = (v > 1.0f) ? 1.0f : 0.f;
      po[t] = sp;
    }
  }
}

// ---------------- launcher ---------------------------------------------------
extern "C" void kernel_launch(void* const* d_in, const int* in_sizes, int n_in,
                              void* d_out, int out_size) {
  const float *X = nullptr, *W1 = nullptr, *b1 = nullptr, *W2 = nullptr,
              *b2 = nullptr, *W3 = nullptr, *b3 = nullptr;
  for (int i = 0; i < n_in; i++) {
    switch (in_sizes[i]) {
      case 20070400: X  = (const float*)d_in[i]; break;  // 256*784*100
      case 784000:   W1 = (const float*)d_in[i]; break;  // 1000*784
      case 1000:     b1 = (const float*)d_in[i]; break;
      case 250000:   W2 = (const float*)d_in[i]; break;  // 500*500
      case 500:      b2 = (const float*)d_in[i]; break;
      case 5000:     W3 = (const float*)d_in[i]; break;  // 10*500
      case 10:       b3 = (const float*)d_in[i]; break;
      default: break;
    }
  }
  float* out = (float*)d_out;

  xT_kernel<<<dim3(100, FIN), 256>>>(X);
  w1T_kernel<<<FIN, 256>>>(W1);
  w2T_kernel<<<512, 256>>>(W2);
  gemm1_kernel<<<dim3(16, 200), 128>>>(b1);
  iir_kernel<<<2000, 256>>>();
  gemm2_kernel<<<dim3(8, 200), 128>>>(b2);
  lifiir_kernel<<<2000, 256>>>();
  gemm3_kernel<<<400, 128>>>(W3, b3);
  lif3_out_kernel<<<40, 256>>>(out);
}